// round 12
// baseline (speedup 1.0000x reference)
#include <cuda_runtime.h>
#include <stdint.h>

// EmbeddingDropout, fused single kernel (FINAL — best measured config):
// out[tok,:] = W[words[tok],:] * keep(words[tok])
// keep(v) via JAX partitionable threefry2x32, key=(0,42):
//   (o0,o1) = threefry2x32(x0=0, x1=v); bits = o0^o1
//   u = bitcast((bits>>9)|0x3f800000)-1 ; keep = (u>=0.1) ? 1/0.9 : 0
//
// Measured design rationale (GB300, rounds 2-11):
//  - One warp per token, 8x LDG.128 per lane: coalesced 4KB row copy.
//  - Warp-uniform keep computed BEFORE the gather: dropped rows (~10%)
//    skip the W read entirely -> -26MB DRAM, -4.2us (R6 win).
//  - Plain LDG for W (__ldcg: +12 regs, zero bandwidth gain — R7/R8).
//  - __stcs for out: evict-first but keeps L2 write-coalescing.
//    (__stwt regressed: bypassing L2 write-combining inflated effective
//    DRAM write traffic ~12MB — R10.)
//  - Bandwidth pinned at ~5.9-6.0TB/s for this mixed random-gather-read +
//    stream-write pattern, invariant across occ 54-86%, MLP 8-16,
//    persistent/non-persistent grids (R3-R5,R7,R8). Run-to-run noise
//    band ~±1us (R9 vs R11, identical binary).
//  - Kernel ~6% above minimum-traffic time at measured achievable BW;
//    remaining read slack (~12MB L2 capacity misses) recoverable only
//    via a token-sort pass whose cost exceeds the gain.

#define D_EMB 1024

__device__ __forceinline__ uint32_t rotl32(uint32_t v, int d) {
    return (v << d) | (v >> (32 - d));
}

__device__ __forceinline__ float keep_of_row(uint32_t x1) {
    const uint32_t ks1 = 42u;
    const uint32_t ks2 = 42u ^ 0x1BD11BDAu;
    uint32_t x0 = 0u;
    x1 += ks1;
#define TF_ROUND(r) { x0 += x1; x1 = rotl32(x1, (r)); x1 ^= x0; }
    TF_ROUND(13) TF_ROUND(15) TF_ROUND(26) TF_ROUND(6)
    x0 += ks1; x1 += ks2 + 1u;
    TF_ROUND(17) TF_ROUND(29) TF_ROUND(16) TF_ROUND(24)
    x0 += ks2; x1 += 0u + 2u;
    TF_ROUND(13) TF_ROUND(15) TF_ROUND(26) TF_ROUND(6)
    x0 += 0u; x1 += ks1 + 3u;
    TF_ROUND(17) TF_ROUND(29) TF_ROUND(16) TF_ROUND(24)
    x0 += ks1; x1 += ks2 + 4u;
    TF_ROUND(13) TF_ROUND(15) TF_ROUND(26) TF_ROUND(6)
    x0 += ks2; x1 += 0u + 5u;
#undef TF_ROUND
    uint32_t bits = x0 ^ x1;
    float u = __uint_as_float((bits >> 9) | 0x3f800000u) - 1.0f;
    return (u >= 0.1f) ? (1.0f / 0.9f) : 0.0f;
}

// One warp per token: lane l handles float4 slots l, l+32, ..., l+224.
__global__ void __launch_bounds__(256)
gather_kernel(const int* __restrict__ words,
              const float* __restrict__ W,
              float* __restrict__ out,
              int n_tokens) {
    int warp_id = (blockIdx.x * blockDim.x + threadIdx.x) >> 5;
    int lane = threadIdx.x & 31;
    if (warp_id >= n_tokens) return;

    int row = __ldg(&words[warp_id]);
    float k = keep_of_row((uint32_t)row);

    float4* __restrict__ dst =
        reinterpret_cast<float4*>(out + (size_t)warp_id * D_EMB);

    if (k == 0.0f) {
        // Dropped row: no W read, just stream zeros.
        float4 z = make_float4(0.f, 0.f, 0.f, 0.f);
#pragma unroll
        for (int j = 0; j < 8; j++)
            __stcs(&dst[lane + 32 * j], z);
        return;
    }

    const float4* __restrict__ src =
        reinterpret_cast<const float4*>(W + (size_t)row * D_EMB);
    float4 v[8];
#pragma unroll
    for (int j = 0; j < 8; j++)
        v[j] = src[lane + 32 * j];
#pragma unroll
    for (int j = 0; j < 8; j++) {
        v[j].x *= k; v[j].y *= k; v[j].z *= k; v[j].w *= k;
        __stcs(&dst[lane + 32 * j], v[j]);
    }
}

extern "C" void kernel_launch(void* const* d_in, const int* in_sizes, int n_in,
                              void* d_out, int out_size) {
    const int*   words = (const int*)d_in[0];   // [32, 2048] int32
    const float* W     = (const float*)d_in[1]; // [50257, 1024] f32
    float*       out   = (float*)d_out;         // [32, 2048, 1024] f32

    int n_tokens = in_sizes[0];                 // 65536
    // 8 warps (= 8 tokens) per 256-thread block
    int blocks = (n_tokens + 7) / 8;
    gather_kernel<<<blocks, 256>>>(words, W, out, n_tokens);
}

// round 13
// speedup vs baseline: 1.0186x; 1.0186x over previous
#include <cuda_runtime.h>
#include <stdint.h>

// EmbeddingDropout, fused single kernel (FINAL — best measured config):
// out[tok,:] = W[words[tok],:] * keep(words[tok])
// keep(v) via JAX partitionable threefry2x32, key=(0,42):
//   (o0,o1) = threefry2x32(x0=0, x1=v); bits = o0^o1
//   u = bitcast((bits>>9)|0x3f800000)-1 ; keep = (u>=0.1) ? 1/0.9 : 0
//
// Measured design rationale (GB300, rounds 2-12):
//  - One warp per token, 8x LDG.128 per lane: coalesced 4KB row copy.
//  - Warp-uniform keep computed BEFORE the gather: dropped rows (~10%)
//    skip the W read entirely -> -26MB DRAM, -4.2us (R6 win).
//  - Plain LDG for W (__ldcg: +12 regs, zero bandwidth gain — R7/R8).
//  - __stcs for out: evict-first but keeps L2 write-coalescing.
//    (__stwt regressed: bypassing L2 write-combining inflated effective
//    DRAM write traffic ~12MB — R10.)
//  - Bandwidth pinned at ~5.9-6.0TB/s for this mixed random-gather-read +
//    stream-write pattern, invariant across occ 54-86%, MLP 8-16,
//    persistent/non-persistent grids (R3-R5,R7,R8). Identical-binary
//    noise band ~±1us (R9/R11/R12).
//  - Kernel ~6% above minimum-traffic time at measured achievable BW;
//    remaining read slack (~12MB L2 capacity misses) recoverable only
//    via a token-sort pass whose cost exceeds the gain.

#define D_EMB 1024

__device__ __forceinline__ uint32_t rotl32(uint32_t v, int d) {
    return (v << d) | (v >> (32 - d));
}

__device__ __forceinline__ float keep_of_row(uint32_t x1) {
    const uint32_t ks1 = 42u;
    const uint32_t ks2 = 42u ^ 0x1BD11BDAu;
    uint32_t x0 = 0u;
    x1 += ks1;
#define TF_ROUND(r) { x0 += x1; x1 = rotl32(x1, (r)); x1 ^= x0; }
    TF_ROUND(13) TF_ROUND(15) TF_ROUND(26) TF_ROUND(6)
    x0 += ks1; x1 += ks2 + 1u;
    TF_ROUND(17) TF_ROUND(29) TF_ROUND(16) TF_ROUND(24)
    x0 += ks2; x1 += 0u + 2u;
    TF_ROUND(13) TF_ROUND(15) TF_ROUND(26) TF_ROUND(6)
    x0 += 0u; x1 += ks1 + 3u;
    TF_ROUND(17) TF_ROUND(29) TF_ROUND(16) TF_ROUND(24)
    x0 += ks1; x1 += ks2 + 4u;
    TF_ROUND(13) TF_ROUND(15) TF_ROUND(26) TF_ROUND(6)
    x0 += ks2; x1 += 0u + 5u;
#undef TF_ROUND
    uint32_t bits = x0 ^ x1;
    float u = __uint_as_float((bits >> 9) | 0x3f800000u) - 1.0f;
    return (u >= 0.1f) ? (1.0f / 0.9f) : 0.0f;
}

// One warp per token: lane l handles float4 slots l, l+32, ..., l+224.
__global__ void __launch_bounds__(256)
gather_kernel(const int* __restrict__ words,
              const float* __restrict__ W,
              float* __restrict__ out,
              int n_tokens) {
    int warp_id = (blockIdx.x * blockDim.x + threadIdx.x) >> 5;
    int lane = threadIdx.x & 31;
    if (warp_id >= n_tokens) return;

    int row = __ldg(&words[warp_id]);
    float k = keep_of_row((uint32_t)row);

    float4* __restrict__ dst =
        reinterpret_cast<float4*>(out + (size_t)warp_id * D_EMB);

    if (k == 0.0f) {
        // Dropped row: no W read, just stream zeros.
        float4 z = make_float4(0.f, 0.f, 0.f, 0.f);
#pragma unroll
        for (int j = 0; j < 8; j++)
            __stcs(&dst[lane + 32 * j], z);
        return;
    }

    const float4* __restrict__ src =
        reinterpret_cast<const float4*>(W + (size_t)row * D_EMB);
    float4 v[8];
#pragma unroll
    for (int j = 0; j < 8; j++)
        v[j] = src[lane + 32 * j];
#pragma unroll
    for (int j = 0; j < 8; j++) {
        v[j].x *= k; v[j].y *= k; v[j].z *= k; v[j].w *= k;
        __stcs(&dst[lane + 32 * j], v[j]);
    }
}

extern "C" void kernel_launch(void* const* d_in, const int* in_sizes, int n_in,
                              void* d_out, int out_size) {
    const int*   words = (const int*)d_in[0];   // [32, 2048] int32
    const float* W     = (const float*)d_in[1]; // [50257, 1024] f32
    float*       out   = (float*)d_out;         // [32, 2048, 1024] f32

    int n_tokens = in_sizes[0];                 // 65536
    // 8 warps (= 8 tokens) per 256-thread block
    int blocks = (n_tokens + 7) / 8;
    gather_kernel<<<blocks, 256>>>(words, W, out, n_tokens);
}